// round 17
// baseline (speedup 1.0000x reference)
#include <cuda_runtime.h>
#include <cstdint>

#define NN 8192u
#define MD 8193u
#define MM 67125249u           // 8193*8193
#define BIAS_START 67117056u   // 8192*8193 (start of last row within a matrix)
#define DIAG_STRIDE 8194u      // diag element i at i*(MD+1) within a matrix
#define CLCU 16384u            // 2*NN floats of cl/cu before the matrices
#define TOTAL 134266882u       // CLCU + 2*MM
#define BODY_END 134266880u    // TOTAL rounded down to multiple of 8
#define NBODY 16783360u        // BODY_END / 8 chunks of 8 floats
#define NCTA 148u
#define TPB 1024u
#define CPC 113402u            // ceil(NBODY / NCTA) chunks per CTA (contiguous span)
#define EPS_ALPHA 1e-5f

struct Relax { float cl, cu, dl, du, bl, bu; };

__device__ __forceinline__ Relax relax(float l, float u)
{
    float den_ul = (u > l)    ? (u - l)    : 1.0f;
    float den_6l = (l < 6.0f) ? (6.0f - l) : 1.0f;
    float u_safe = (u > 0.0f) ? u          : 1.0f;

    bool mA = (u > 0.0f) && (u <= 6.0f) && (l >= 0.0f);
    bool mB = (u > 0.0f) && (u <= 6.0f) && (l <  0.0f);
    bool mC = (u > 6.0f) && (l <= 0.0f);
    bool mD = (u > 6.0f) && (l >  0.0f) && (l <= 6.0f);
    bool mE = (l > 6.0f);

    float alpha_B = (u < -l) ? EPS_ALPHA : 1.0f;
    float lam_B   = u / den_ul;
    float aU_C    = ((u - 6.0f) < (6.0f - l)) ? (6.0f / den_6l) : EPS_ALPHA;
    float aL_C    = (u < -l) ? EPS_ALPHA : (6.0f / u_safe);
    float aU_D    = ((u - 6.0f) < (6.0f - l)) ? 1.0f : EPS_ALPHA;
    float aL_D    = (6.0f - l) / den_ul;

    float fA = mA ? 1.0f : 0.0f;
    float fB = mB ? 1.0f : 0.0f;
    float fC = mC ? 1.0f : 0.0f;
    float fD = mD ? 1.0f : 0.0f;
    float fE = mE ? 1.0f : 0.0f;

    Relax r;
    r.du = fA * 1.0f + fB * lam_B   + fC * aU_C + fD * aU_D;
    r.dl = fA * 1.0f + fB * alpha_B + fC * aL_C + fD * aL_D;
    r.bu = fB * (-lam_B * l)
         + fC * (6.0f * (1.0f - aU_C))
         + fD * (6.0f * (1.0f - aU_D))
         + fE * 6.0f;
    r.bl = fD * (l * (1.0f - aL_D)) + fE * 6.0f;
    r.cu = fA * u + fB * u
         + fC * (6.0f + aU_C * (u - 6.0f))
         + fD * (6.0f + aU_D * (u - 6.0f))
         + fE * 6.0f;
    r.cl = fA * l + fB * (alpha_B * l) + fC * (aL_C * l)
         + fD * l + fE * 6.0f;
    return r;
}

__device__ __forceinline__ float mat_value(unsigned p, bool isL,
                                           const float* __restrict__ lower,
                                           const float* __restrict__ upper)
{
    if (p >= BIAS_START) {
        unsigned col = p - BIAS_START;
        if (col == NN) return 1.0f;           // [-1,-1] corner
        Relax r = relax(lower[col], upper[col]);
        return isL ? r.bl : r.bu;
    }
    unsigned row = p / DIAG_STRIDE;
    if (p == row * DIAG_STRIDE) {
        Relax r = relax(lower[row], upper[row]);
        return isL ? r.dl : r.du;
    }
    return 0.0f;
}

__device__ __forceinline__ float out_value(unsigned oe,
                                           const float* __restrict__ lower,
                                           const float* __restrict__ upper)
{
    if (oe < CLCU) {
        unsigned i = oe & (NN - 1u);
        Relax r = relax(lower[i], upper[i]);
        return (oe < NN) ? r.cl : r.cu;
    }
    unsigned r = oe - CLCU;
    if (r < MM) return mat_value(r, true, lower, upper);
    return mat_value(r - MM, false, lower, upper);
}

__device__ __forceinline__ void st256(float* p, const float4& a, const float4& b)
{
    asm volatile("st.global.v8.f32 [%0], {%1,%2,%3,%4,%5,%6,%7,%8};"
                 :: "l"(p),
                    "f"(a.x), "f"(a.y), "f"(a.z), "f"(a.w),
                    "f"(b.x), "f"(b.y), "f"(b.z), "f"(b.w)
                 : "memory");
}

// One CTA per SM; each CTA sweeps ONE contiguous ~3.6MB span front-to-back in
// 32KB steps (1024 threads x 32B). Chip-wide: 148 linear write streams.
__global__ void __launch_bounds__(TPB, 1)
relu6_sweep(const float* __restrict__ lower,
            const float* __restrict__ upper,
            float* __restrict__ out)
{
    unsigned begin = blockIdx.x * CPC;
    unsigned end   = begin + CPC;
    if (end > NBODY) end = NBODY;

    for (unsigned c = begin + threadIdx.x; c < end; c += TPB) {
        unsigned o = c * 8u;

        // Pure-zero test: chunk fully inside one matrix, no diag/bias element.
        unsigned r = o - CLCU;                     // valid when o >= CLCU
        bool inL = (o >= CLCU) & (r + 8u <= MM);
        bool inU = (r >= MM) & (r + 8u <= 2u * MM);
        unsigned p = inU ? (r - MM) : r;
        unsigned q = (p + 7u) / DIAG_STRIDE;       // constant divide
        bool hasDiag = (q * DIAG_STRIDE >= p);     // multiple of 8194 in [p, p+8)
        bool hasBias = (p + 7u >= BIAS_START);

        float4 a, b;
        if ((inL | inU) & !hasDiag & !hasBias) {
            a = make_float4(0.f, 0.f, 0.f, 0.f);
            b = a;
        } else {
            a.x = out_value(o + 0u, lower, upper);
            a.y = out_value(o + 1u, lower, upper);
            a.z = out_value(o + 2u, lower, upper);
            a.w = out_value(o + 3u, lower, upper);
            b.x = out_value(o + 4u, lower, upper);
            b.y = out_value(o + 5u, lower, upper);
            b.z = out_value(o + 6u, lower, upper);
            b.w = out_value(o + 7u, lower, upper);
        }
        st256(out + o, a, b);
    }

    // Tail: TOTAL % 8 == 2 — last block, one thread.
    if (blockIdx.x == NCTA - 1u && threadIdx.x == 0u) {
        for (unsigned oe = BODY_END; oe < TOTAL; ++oe)
            out[oe] = out_value(oe, lower, upper);
    }
}

extern "C" void kernel_launch(void* const* d_in, const int* in_sizes, int n_in,
                              void* d_out, int out_size)
{
    const float* lower = (const float*)d_in[0];
    const float* upper = (const float*)d_in[1];
    float* out = (float*)d_out;

    relu6_sweep<<<NCTA, TPB>>>(lower, upper, out);
}